// round 14
// baseline (speedup 1.0000x reference)
#include <cuda_runtime.h>
#include <cuda_fp16.h>
#include <cstdint>
#include <cmath>

// SNRContrastiveLoss: N=8192, D=256, NUM_CLASSES=512
// Round 11 design (resubmit after infra failure): fp16 mma.sync + ldmatrix;
// triangular 2080-block grid, 3-stage single-sync cp.async ring, last-block
// fused finalize (k_fin removed).
// distmat_ij = (s_i + s_j - 2*g_ij - (m_i-m_j)^2) / (s_i - m_i^2)   (corr cancels)

#define NROWS 8192
#define DDIM  256
#define POS_MARGIN 0.01f
#define NEG_MARGIN 0.2f

#define BMN 128
#define BK  64                      // halves per stage (128 B rows)
#define NSTG (DDIM / BK)            // 4 K-iterations
#define NTB  (NROWS / BMN)          // 64 tile rows
#define NTILES (NTB * (NTB + 1) / 2)// 2080 upper-tri tiles
#define TILE_BYTES (BMN * BK * 2)   // 16 KB
#define STAGE_BYTES (2 * TILE_BYTES)// A+B = 32 KB
#define NBUF 3
#define DYN_SMEM (NBUF * STAGE_BYTES) // 96 KB ring

__device__ __half g_eh[NROWS * DDIM];  // fp16 normalized embeddings (4 MB)
__device__ float  g_s[NROWS];
__device__ float  g_m[NROWS];
__device__ float  g_iv[NROWS];
__device__ int    g_lab[NROWS];
__device__ double g_acc[5];            // pos_sum, pos_cnt, neg_sum, neg_cnt, reg_sum
__device__ int    g_is64;
__device__ int    g_done;

// ---------------- helpers ----------------
__device__ __forceinline__ uint32_t smem_u32(const void* p) {
    uint32_t a;
    asm("{ .reg .u64 t; cvta.to.shared.u64 t, %1; cvt.u32.u64 %0, t; }" : "=r"(a) : "l"(p));
    return a;
}
__device__ __forceinline__ void cp_async16(uint32_t dst, const void* src) {
    asm volatile("cp.async.cg.shared.global [%0], [%1], 16;" ::
                 "r"(dst), "l"(__cvta_generic_to_global(src)) : "memory");
}
__device__ __forceinline__ void cp_commit() {
    asm volatile("cp.async.commit_group;" ::: "memory");
}
template <int N>
__device__ __forceinline__ void cp_wait() {
    asm volatile("cp.async.wait_group %0;" :: "n"(N) : "memory");
}
__device__ __forceinline__ void ldsm_x4(uint32_t* r, uint32_t addr) {
    asm volatile("ldmatrix.sync.aligned.m8n8.x4.shared.b16 {%0,%1,%2,%3}, [%4];"
                 : "=r"(r[0]), "=r"(r[1]), "=r"(r[2]), "=r"(r[3]) : "r"(addr));
}
__device__ __forceinline__ void mma_f16(float* c, const uint32_t* a, uint32_t b0, uint32_t b1) {
    asm volatile(
        "mma.sync.aligned.m16n8k16.row.col.f32.f16.f16.f32 "
        "{%0,%1,%2,%3}, {%4,%5,%6,%7}, {%8,%9}, {%0,%1,%2,%3};"
        : "+f"(c[0]), "+f"(c[1]), "+f"(c[2]), "+f"(c[3])
        : "r"(a[0]), "r"(a[1]), "r"(a[2]), "r"(a[3]), "r"(b0), "r"(b1));
}
__device__ __forceinline__ float warpSumF(float v) {
    #pragma unroll
    for (int o = 16; o > 0; o >>= 1) v += __shfl_xor_sync(0xffffffffu, v, o);
    return v;
}

// ---------------------------------------------------------------------------
// Kernel 0: zero accumulators + detect int64 vs int32 labels (odd words all 0).
// ---------------------------------------------------------------------------
__global__ void k_init(const int* __restrict__ lab32) {
    __shared__ int nz;
    int t = threadIdx.x;
    if (t == 0) nz = 0;
    __syncthreads();
    int loc = 0;
    for (int i = 2 * t + 1; i < NROWS; i += 2 * blockDim.x) loc |= lab32[i];
    if (loc) atomicOr(&nz, 1);
    __syncthreads();
    if (t == 0) {
        g_is64 = (nz == 0) ? 1 : 0;
        g_done = 0;
        #pragma unroll
        for (int j = 0; j < 5; j++) g_acc[j] = 0.0;
    }
}

// ---------------------------------------------------------------------------
// Kernel 1: per-row normalize + stats, fp16 store.
// ---------------------------------------------------------------------------
__global__ __launch_bounds__(256) void k_prep(const float* __restrict__ x,
                                              const int* __restrict__ lab32) {
    int row = blockIdx.x;
    int t = threadIdx.x;
    float v = x[row * DDIM + t];

    __shared__ float sh[8];
    float s2 = warpSumF(v * v);
    if ((t & 31) == 0) sh[t >> 5] = s2;
    __syncthreads();
    if (t < 32) {
        float z = (t < 8) ? sh[t] : 0.0f;
        z = warpSumF(z);
        if (t == 0) sh[0] = z;
    }
    __syncthreads();
    float rinv = rsqrtf(sh[0]);
    float e = v * rinv;
    g_eh[row * DDIM + t] = __float2half_rn(e);
    __syncthreads();

    __shared__ float she[8], she2[8];
    float re = warpSumF(e);
    float re2 = warpSumF(e * e);
    if ((t & 31) == 0) { she[t >> 5] = re; she2[t >> 5] = re2; }
    __syncthreads();
    if (t == 0) {
        float se = 0.0f, se2 = 0.0f;
        #pragma unroll
        for (int i = 0; i < 8; i++) { se += she[i]; se2 += she2[i]; }
        float m = se * (1.0f / DDIM);
        float s = se2 * (1.0f / DDIM);
        g_s[row] = s;
        g_m[row] = m;
        g_iv[row] = 1.0f / (s - m * m);
        g_lab[row] = g_is64 ? lab32[2 * row] : lab32[row];
        atomicAdd(&g_acc[4], (double)fabsf(se));
    }
}

// ---------------------------------------------------------------------------
// Kernel 2: fp16 mma.sync 128x128 tile kernel; 2080 triangular blocks;
// 3-buffer cp.async ring with ONE __syncthreads per K-stage; last-block
// finalize writes the scalar output.
// ---------------------------------------------------------------------------
extern __shared__ char dynsmem[];

__device__ __forceinline__ void load_stage(uint32_t abuf, uint32_t bbuf,
                                           const __half* Ab, const __half* Bb,
                                           int k0, int tid) {
    #pragma unroll
    for (int l = 0; l < 4; l++) {
        int f = tid + l * 256;          // 0..1023 chunk id of one 16KB tile
        int r = f >> 3;                 // row 0..127
        int c = f & 7;                  // 16B chunk within 128B row
        uint32_t sw = (uint32_t)(r * 128 + ((c ^ (r & 7)) << 4));
        cp_async16(abuf + sw, Ab + (size_t)r * DDIM + k0 + c * 8);
        cp_async16(bbuf + sw, Bb + (size_t)r * DDIM + k0 + c * 8);
    }
    cp_commit();
}

// address of the 8x8 b16 matrix row for ldmatrix.x4 (A and B share the pattern)
__device__ __forceinline__ uint32_t frag_addr(uint32_t tbuf, int base_row, int kc, int lane) {
    int row = base_row + ((lane >> 3) & 1) * 8 + (lane & 7);
    int chunk = kc + (lane >> 4);
    return tbuf + (uint32_t)(row * 128 + ((chunk ^ (row & 7)) << 4));
}

__global__ __launch_bounds__(256, 2) void k_main(float* __restrict__ out) {
    // triangular decode: tile t -> (bi, bj), bj >= bi. S(b) = b*(2*NTB+1-b)/2
    int t = blockIdx.x;
    int bi = (int)((2 * NTB + 1 - sqrt((double)((2 * NTB + 1) * (2 * NTB + 1) - 8 * t))) * 0.5);
    while (bi > 0 && bi * (2 * NTB + 1 - bi) / 2 > t) bi--;
    while ((bi + 1) * (2 * NTB + 1 - (bi + 1)) / 2 <= t) bi++;
    int bj = bi + (t - bi * (2 * NTB + 1 - bi) / 2);

    int tid = threadIdx.x;
    int warp = tid >> 5;
    int lane = tid & 31;
    int qr = lane >> 2;
    int qc = lane & 3;
    int wm = (warp & 1) * 64;
    int wn = (warp >> 1) * 32;

    uint32_t sbase = smem_u32(dynsmem);
    const __half* Ab = g_eh + (size_t)bi * BMN * DDIM;
    const __half* Bb = g_eh + (size_t)bj * BMN * DDIM;

    float c[4][4][4];
    #pragma unroll
    for (int mi = 0; mi < 4; mi++)
        #pragma unroll
        for (int ni = 0; ni < 4; ni++)
            #pragma unroll
            for (int h = 0; h < 4; h++) c[mi][ni][h] = 0.0f;

    // prologue: stages 0,1 into bufs 0,1
    load_stage(sbase, sbase + TILE_BYTES, Ab, Bb, 0, tid);
    load_stage(sbase + STAGE_BYTES, sbase + STAGE_BYTES + TILE_BYTES, Ab, Bb, BK, tid);

    #pragma unroll
    for (int k = 0; k < NSTG; k++) {
        if (k < NSTG - 1) cp_wait<1>(); else cp_wait<0>();
        __syncthreads();   // single barrier per stage (3-buffer ring makes the
                           // write-after-read hazard span a full iteration)

        if (k + 2 < NSTG) {
            uint32_t nb = sbase + (uint32_t)((k + 2) % NBUF) * STAGE_BYTES;
            load_stage(nb, nb + TILE_BYTES, Ab, Bb, (k + 2) * BK, tid);
        }

        uint32_t abuf = sbase + (uint32_t)(k % NBUF) * STAGE_BYTES;
        uint32_t bbuf = abuf + TILE_BYTES;

        #pragma unroll
        for (int kt = 0; kt < BK / 16; kt++) {        // 4 k-subtiles of 16
            int kc = kt * 2;
            uint32_t a[4][4], b[2][4];
            #pragma unroll
            for (int mi = 0; mi < 4; mi++)
                ldsm_x4(a[mi], frag_addr(abuf, wm + mi * 16, kc, lane));
            #pragma unroll
            for (int nj = 0; nj < 2; nj++)
                ldsm_x4(b[nj], frag_addr(bbuf, wn + nj * 16, kc, lane));
            #pragma unroll
            for (int mi = 0; mi < 4; mi++)
                #pragma unroll
                for (int ni = 0; ni < 4; ni++) {
                    int nj = ni >> 1, sel = ni & 1;
                    mma_f16(c[mi][ni], a[mi], b[nj][sel], b[nj][sel + 2]);
                }
        }
    }

    // ---- epilogue ----
    // C frag: c0:(qr,2qc) c1:(qr,2qc+1) c2:(qr+8,2qc) c3:(qr+8,2qc+1)
    int rbase = bi * BMN + wm;
    int cbase = bj * BMN + wn;

    float sr[8], mr[8], ivr[8]; int lr[8];
    float sc[8], mc[8], ivc[8]; int lc[8];
    #pragma unroll
    for (int mi = 0; mi < 4; mi++) {
        int r = rbase + mi * 16 + qr;
        sr[2*mi]   = g_s[r];   mr[2*mi]   = g_m[r];
        ivr[2*mi]  = g_iv[r];  lr[2*mi]   = g_lab[r];
        sr[2*mi+1] = g_s[r+8]; mr[2*mi+1] = g_m[r+8];
        ivr[2*mi+1]= g_iv[r+8];lr[2*mi+1] = g_lab[r+8];
    }
    #pragma unroll
    for (int ni = 0; ni < 4; ni++) {
        int cix = cbase + ni * 8 + 2 * qc;
        sc[2*ni]   = g_s[cix];   mc[2*ni]   = g_m[cix];
        ivc[2*ni]  = g_iv[cix];  lc[2*ni]   = g_lab[cix];
        sc[2*ni+1] = g_s[cix+1]; mc[2*ni+1] = g_m[cix+1];
        ivc[2*ni+1]= g_iv[cix+1];lc[2*ni+1] = g_lab[cix+1];
    }

    float psum = 0.0f, nsum = 0.0f, pcnt = 0.0f, ncnt = 0.0f;
    bool offdiag = (bi != bj);

    #pragma unroll
    for (int mi = 0; mi < 4; mi++) {
        #pragma unroll
        for (int ni = 0; ni < 4; ni++) {
            #pragma unroll
            for (int h = 0; h < 4; h++) {
                int ri = 2 * mi + (h >> 1);
                int ci = 2 * ni + (h & 1);
                int r  = rbase + mi * 16 + qr + (h >> 1) * 8;
                int cg = cbase + ni * 8 + 2 * qc + (h & 1);
                if (r == cg) continue;
                float g = c[mi][ni][h] * (1.0f / DDIM);
                float dm = mr[ri] - mc[ci];
                float num = sr[ri] + sc[ci] - 2.0f * g - dm * dm;
                bool same = (lr[ri] == lc[ci]);
                float d1 = num * ivr[ri];
                if (same) {
                    float p = d1 - POS_MARGIN;
                    if (p > 0.0f) { psum += p; pcnt += 1.0f; }
                } else {
                    float q = NEG_MARGIN - d1;
                    if (q > 0.0f) { nsum += q; ncnt += 1.0f; }
                }
                if (offdiag) {
                    float d2 = num * ivc[ci];
                    if (same) {
                        float p = d2 - POS_MARGIN;
                        if (p > 0.0f) { psum += p; pcnt += 1.0f; }
                    } else {
                        float q = NEG_MARGIN - d2;
                        if (q > 0.0f) { nsum += q; ncnt += 1.0f; }
                    }
                }
            }
        }
    }

    psum = warpSumF(psum); nsum = warpSumF(nsum);
    pcnt = warpSumF(pcnt); ncnt = warpSumF(ncnt);

    __shared__ float red[4][8];
    if (lane == 0) {
        red[0][warp] = psum; red[1][warp] = pcnt;
        red[2][warp] = nsum; red[3][warp] = ncnt;
    }
    __syncthreads();
    if (tid < 4) {
        float s = 0.0f;
        #pragma unroll
        for (int w = 0; w < 8; w++) s += red[tid][w];
        atomicAdd(&g_acc[tid], (double)s);
    }
    __syncthreads();

    // last-block finalize (replaces the k_fin launch)
    if (tid == 0) {
        __threadfence();
        int prev = atomicAdd(&g_done, 1);
        if (prev == NTILES - 1) {
            __threadfence();
            double pos = g_acc[0] / (g_acc[1] + 1e-12);
            double neg = g_acc[2] / (g_acc[3] + 1e-12);
            double reg = (g_acc[4] / (double)NROWS) * 0.1;
            out[0] = (float)(pos + neg + reg);
        }
    }
}

extern "C" void kernel_launch(void* const* d_in, const int* in_sizes, int n_in,
                              void* d_out, int out_size) {
    const float* embeds = (const float*)d_in[0];
    const int*   lab32  = (const int*)d_in[1];   // dtype detected at runtime
    float* out = (float*)d_out;
    (void)in_sizes; (void)n_in; (void)out_size;

    cudaFuncSetAttribute(k_main, cudaFuncAttributeMaxDynamicSharedMemorySize, DYN_SMEM);

    k_init<<<1, 256>>>(lab32);
    k_prep<<<NROWS, 256>>>(embeds, lab32);
    k_main<<<NTILES, 256, DYN_SMEM>>>(out);
}

// round 17
// speedup vs baseline: 1.1202x; 1.1202x over previous
#include <cuda_runtime.h>
#include <cuda_fp16.h>
#include <cstdint>

// SNRContrastiveLoss: N=8192, D=256, NUM_CLASSES=512
// Round 15: round-10 mainloop (best measured: 98.6us) + fused finalize
// (k_fin launch removed) + warp-per-row k_prep (no block barriers).
// distmat_ij = (s_i + s_j - 2*g_ij - (m_i-m_j)^2) / (s_i - m_i^2)   (corr cancels)

#define NROWS 8192
#define DDIM  256
#define POS_MARGIN 0.01f
#define NEG_MARGIN 0.2f

#define BMN 128
#define BK  64                      // halves per stage (128 B rows)
#define NSTG (DDIM / BK)            // 4
#define NTB  (NROWS / BMN)          // 64
#define NTILES (NTB * (NTB + 1) / 2)// 2080 alive (upper-tri) blocks
#define TILE_BYTES (BMN * BK * 2)   // 16 KB
#define STAGE_BYTES (2 * TILE_BYTES)// A+B = 32 KB
#define DYN_SMEM (2 * STAGE_BYTES)  // 64 KB double buffer

__device__ __half g_eh[NROWS * DDIM];  // fp16 normalized embeddings (4 MB)
__device__ float  g_s[NROWS];
__device__ float  g_m[NROWS];
__device__ float  g_iv[NROWS];
__device__ int    g_lab[NROWS];
__device__ double g_acc[5];            // pos_sum, pos_cnt, neg_sum, neg_cnt, reg_sum
__device__ int    g_is64;
__device__ int    g_done;

// ---------------- helpers ----------------
__device__ __forceinline__ uint32_t smem_u32(const void* p) {
    uint32_t a;
    asm("{ .reg .u64 t; cvta.to.shared.u64 t, %1; cvt.u32.u64 %0, t; }" : "=r"(a) : "l"(p));
    return a;
}
__device__ __forceinline__ void cp_async16(uint32_t dst, const void* src) {
    asm volatile("cp.async.cg.shared.global [%0], [%1], 16;" ::
                 "r"(dst), "l"(__cvta_generic_to_global(src)) : "memory");
}
__device__ __forceinline__ void cp_commit() {
    asm volatile("cp.async.commit_group;" ::: "memory");
}
template <int N>
__device__ __forceinline__ void cp_wait() {
    asm volatile("cp.async.wait_group %0;" :: "n"(N) : "memory");
}
__device__ __forceinline__ void ldsm_x4(uint32_t* r, uint32_t addr) {
    asm volatile("ldmatrix.sync.aligned.m8n8.x4.shared.b16 {%0,%1,%2,%3}, [%4];"
                 : "=r"(r[0]), "=r"(r[1]), "=r"(r[2]), "=r"(r[3]) : "r"(addr));
}
__device__ __forceinline__ void mma_f16(float* c, const uint32_t* a, uint32_t b0, uint32_t b1) {
    asm volatile(
        "mma.sync.aligned.m16n8k16.row.col.f32.f16.f16.f32 "
        "{%0,%1,%2,%3}, {%4,%5,%6,%7}, {%8,%9}, {%0,%1,%2,%3};"
        : "+f"(c[0]), "+f"(c[1]), "+f"(c[2]), "+f"(c[3])
        : "r"(a[0]), "r"(a[1]), "r"(a[2]), "r"(a[3]), "r"(b0), "r"(b1));
}
__device__ __forceinline__ float warpSumF(float v) {
    #pragma unroll
    for (int o = 16; o > 0; o >>= 1) v += __shfl_xor_sync(0xffffffffu, v, o);
    return v;
}

// ---------------------------------------------------------------------------
// Kernel 0: zero accumulators + detect int64 vs int32 labels (odd words all 0).
// ---------------------------------------------------------------------------
__global__ void k_init(const int* __restrict__ lab32) {
    __shared__ int nz;
    int t = threadIdx.x;
    if (t == 0) nz = 0;
    __syncthreads();
    int loc = 0;
    for (int i = 2 * t + 1; i < NROWS; i += 2 * blockDim.x) loc |= lab32[i];
    if (loc) atomicOr(&nz, 1);
    __syncthreads();
    if (t == 0) {
        g_is64 = (nz == 0) ? 1 : 0;
        g_done = 0;
        #pragma unroll
        for (int j = 0; j < 5; j++) g_acc[j] = 0.0;
    }
}

// ---------------------------------------------------------------------------
// Kernel 1: warp-per-row normalize + stats (no block barriers).
// 256 threads = 8 warps = 8 rows per block; lane handles 8 consecutive floats.
// ---------------------------------------------------------------------------
__global__ __launch_bounds__(256) void k_prep(const float* __restrict__ x,
                                              const int* __restrict__ lab32) {
    int wid = threadIdx.x >> 5;
    int lane = threadIdx.x & 31;
    int row = blockIdx.x * 8 + wid;

    const float4* xp = (const float4*)(x + (size_t)row * DDIM) + lane * 2;
    float4 v0 = xp[0], v1 = xp[1];

    float ss = v0.x*v0.x + v0.y*v0.y + v0.z*v0.z + v0.w*v0.w
             + v1.x*v1.x + v1.y*v1.y + v1.z*v1.z + v1.w*v1.w;
    ss = warpSumF(ss);
    float rinv = rsqrtf(ss);

    float e[8] = { v0.x*rinv, v0.y*rinv, v0.z*rinv, v0.w*rinv,
                   v1.x*rinv, v1.y*rinv, v1.z*rinv, v1.w*rinv };

    // pack 8 halves into one 16B store
    __half2 h0 = __floats2half2_rn(e[0], e[1]);
    __half2 h1 = __floats2half2_rn(e[2], e[3]);
    __half2 h2 = __floats2half2_rn(e[4], e[5]);
    __half2 h3 = __floats2half2_rn(e[6], e[7]);
    uint4 pack;
    pack.x = *(uint32_t*)&h0; pack.y = *(uint32_t*)&h1;
    pack.z = *(uint32_t*)&h2; pack.w = *(uint32_t*)&h3;
    *((uint4*)(g_eh + (size_t)row * DDIM) + lane) = pack;

    float re = 0.0f, re2 = 0.0f;
    #pragma unroll
    for (int i = 0; i < 8; i++) { re += e[i]; re2 += e[i] * e[i]; }
    re = warpSumF(re);
    re2 = warpSumF(re2);

    if (lane == 0) {
        float m = re * (1.0f / DDIM);
        float s = re2 * (1.0f / DDIM);
        g_s[row] = s;
        g_m[row] = m;
        g_iv[row] = 1.0f / (s - m * m);
        g_lab[row] = g_is64 ? lab32[2 * row] : lab32[row];
        atomicAdd(&g_acc[4], (double)fabsf(re));
    }
}

// ---------------------------------------------------------------------------
// Kernel 2: fp16 mma.sync 128x128 tile kernel (round-10 mainloop verbatim);
// upper-triangular blocks of a 2D grid; last-block fused finalize.
// ---------------------------------------------------------------------------
extern __shared__ char dynsmem[];

__device__ __forceinline__ void load_stage(uint32_t abuf, uint32_t bbuf,
                                           const __half* Ab, const __half* Bb,
                                           int k0, int tid) {
    #pragma unroll
    for (int l = 0; l < 4; l++) {
        int f = tid + l * 256;          // 0..1023 chunk id of one 16KB tile
        int r = f >> 3;                 // row 0..127
        int c = f & 7;                  // 16B chunk within 128B row
        uint32_t sw = (uint32_t)(r * 128 + ((c ^ (r & 7)) << 4));
        cp_async16(abuf + sw, Ab + (size_t)r * DDIM + k0 + c * 8);
        cp_async16(bbuf + sw, Bb + (size_t)r * DDIM + k0 + c * 8);
    }
    cp_commit();
}

// address of the 8x8 b16 matrix row for ldmatrix.x4 (A and B share the pattern)
__device__ __forceinline__ uint32_t frag_addr(uint32_t tbuf, int base_row, int kc, int lane) {
    int row = base_row + ((lane >> 3) & 1) * 8 + (lane & 7);
    int chunk = kc + (lane >> 4);
    return tbuf + (uint32_t)(row * 128 + ((chunk ^ (row & 7)) << 4));
}

__global__ __launch_bounds__(256, 2) void k_main(float* __restrict__ out) {
    int bi = blockIdx.y;
    int bj = blockIdx.x;
    if (bj < bi) return;

    int tid = threadIdx.x;
    int warp = tid >> 5;
    int lane = tid & 31;
    int qr = lane >> 2;
    int qc = lane & 3;
    int wm = (warp & 1) * 64;
    int wn = (warp >> 1) * 32;

    uint32_t sbase = smem_u32(dynsmem);
    const __half* Ab = g_eh + (size_t)bi * BMN * DDIM;
    const __half* Bb = g_eh + (size_t)bj * BMN * DDIM;

    float c[4][4][4];
    #pragma unroll
    for (int mi = 0; mi < 4; mi++)
        #pragma unroll
        for (int ni = 0; ni < 4; ni++)
            #pragma unroll
            for (int h = 0; h < 4; h++) c[mi][ni][h] = 0.0f;

    // prologue: fill both stages
    load_stage(sbase, sbase + TILE_BYTES, Ab, Bb, 0, tid);
    load_stage(sbase + STAGE_BYTES, sbase + STAGE_BYTES + TILE_BYTES, Ab, Bb, BK, tid);

    #pragma unroll
    for (int k = 0; k < NSTG; k++) {
        if (k < NSTG - 1) cp_wait<1>(); else cp_wait<0>();
        __syncthreads();

        uint32_t abuf = sbase + (uint32_t)(k & 1) * STAGE_BYTES;
        uint32_t bbuf = abuf + TILE_BYTES;

        #pragma unroll
        for (int kt = 0; kt < BK / 16; kt++) {        // 4 k-subtiles of 16
            int kc = kt * 2;
            uint32_t a[4][4], b[2][4];
            #pragma unroll
            for (int mi = 0; mi < 4; mi++)
                ldsm_x4(a[mi], frag_addr(abuf, wm + mi * 16, kc, lane));
            #pragma unroll
            for (int nj = 0; nj < 2; nj++)
                ldsm_x4(b[nj], frag_addr(bbuf, wn + nj * 16, kc, lane));
            #pragma unroll
            for (int mi = 0; mi < 4; mi++)
                #pragma unroll
                for (int ni = 0; ni < 4; ni++) {
                    int nj = ni >> 1, sel = ni & 1;
                    mma_f16(c[mi][ni], a[mi], b[nj][sel], b[nj][sel + 2]);
                }
        }

        if (k + 2 < NSTG) {
            __syncthreads();   // all warps done reading buf (k&1) before refill
            uint32_t nab = sbase + (uint32_t)(k & 1) * STAGE_BYTES;
            load_stage(nab, nab + TILE_BYTES, Ab, Bb, (k + 2) * BK, tid);
        }
    }

    // ---- epilogue ----
    // C frag: c0:(qr,2qc) c1:(qr,2qc+1) c2:(qr+8,2qc) c3:(qr+8,2qc+1)
    int rbase = bi * BMN + wm;
    int cbase = bj * BMN + wn;

    float sr[8], mr[8], ivr[8]; int lr[8];
    float sc[8], mc[8], ivc[8]; int lc[8];
    #pragma unroll
    for (int mi = 0; mi < 4; mi++) {
        int r = rbase + mi * 16 + qr;
        sr[2*mi]   = g_s[r];   mr[2*mi]   = g_m[r];
        ivr[2*mi]  = g_iv[r];  lr[2*mi]   = g_lab[r];
        sr[2*mi+1] = g_s[r+8]; mr[2*mi+1] = g_m[r+8];
        ivr[2*mi+1]= g_iv[r+8];lr[2*mi+1] = g_lab[r+8];
    }
    #pragma unroll
    for (int ni = 0; ni < 4; ni++) {
        int cix = cbase + ni * 8 + 2 * qc;
        sc[2*ni]   = g_s[cix];   mc[2*ni]   = g_m[cix];
        ivc[2*ni]  = g_iv[cix];  lc[2*ni]   = g_lab[cix];
        sc[2*ni+1] = g_s[cix+1]; mc[2*ni+1] = g_m[cix+1];
        ivc[2*ni+1]= g_iv[cix+1];lc[2*ni+1] = g_lab[cix+1];
    }

    float psum = 0.0f, nsum = 0.0f, pcnt = 0.0f, ncnt = 0.0f;
    bool offdiag = (bi != bj);

    #pragma unroll
    for (int mi = 0; mi < 4; mi++) {
        #pragma unroll
        for (int ni = 0; ni < 4; ni++) {
            #pragma unroll
            for (int h = 0; h < 4; h++) {
                int ri = 2 * mi + (h >> 1);
                int ci = 2 * ni + (h & 1);
                int r  = rbase + mi * 16 + qr + (h >> 1) * 8;
                int cg = cbase + ni * 8 + 2 * qc + (h & 1);
                if (r == cg) continue;
                float g = c[mi][ni][h] * (1.0f / DDIM);
                float dm = mr[ri] - mc[ci];
                float num = sr[ri] + sc[ci] - 2.0f * g - dm * dm;
                bool same = (lr[ri] == lc[ci]);
                float d1 = num * ivr[ri];
                if (same) {
                    float p = d1 - POS_MARGIN;
                    if (p > 0.0f) { psum += p; pcnt += 1.0f; }
                } else {
                    float q = NEG_MARGIN - d1;
                    if (q > 0.0f) { nsum += q; ncnt += 1.0f; }
                }
                if (offdiag) {
                    float d2 = num * ivc[ci];
                    if (same) {
                        float p = d2 - POS_MARGIN;
                        if (p > 0.0f) { psum += p; pcnt += 1.0f; }
                    } else {
                        float q = NEG_MARGIN - d2;
                        if (q > 0.0f) { nsum += q; ncnt += 1.0f; }
                    }
                }
            }
        }
    }

    psum = warpSumF(psum); nsum = warpSumF(nsum);
    pcnt = warpSumF(pcnt); ncnt = warpSumF(ncnt);

    __shared__ float red[4][8];
    if (lane == 0) {
        red[0][warp] = psum; red[1][warp] = pcnt;
        red[2][warp] = nsum; red[3][warp] = ncnt;
    }
    __syncthreads();
    if (tid < 4) {
        float s = 0.0f;
        #pragma unroll
        for (int w = 0; w < 8; w++) s += red[tid][w];
        atomicAdd(&g_acc[tid], (double)s);
    }
    __syncthreads();

    // last-alive-block finalize (replaces the k_fin launch)
    if (tid == 0) {
        __threadfence();
        int prev = atomicAdd(&g_done, 1);
        if (prev == NTILES - 1) {
            __threadfence();
            double pos = g_acc[0] / (g_acc[1] + 1e-12);
            double neg = g_acc[2] / (g_acc[3] + 1e-12);
            double reg = (g_acc[4] / (double)NROWS) * 0.1;
            out[0] = (float)(pos + neg + reg);
        }
    }
}

extern "C" void kernel_launch(void* const* d_in, const int* in_sizes, int n_in,
                              void* d_out, int out_size) {
    const float* embeds = (const float*)d_in[0];
    const int*   lab32  = (const int*)d_in[1];   // dtype detected at runtime
    float* out = (float*)d_out;
    (void)in_sizes; (void)n_in; (void)out_size;

    cudaFuncSetAttribute(k_main, cudaFuncAttributeMaxDynamicSharedMemorySize, DYN_SMEM);

    k_init<<<1, 256>>>(lab32);
    k_prep<<<NROWS / 8, 256>>>(embeds, lab32);
    dim3 grid(NTB, NTB);
    k_main<<<grid, 256, DYN_SMEM>>>(out);
}